// round 15
// baseline (speedup 1.0000x reference)
#include <cuda_runtime.h>
#include <cuda_bf16.h>
#include <math.h>

// ---------------- problem constants ----------------
#define U_NN   50000
#define I_NN   25000
#define DD     64
#define DT     192
#define RR     2
#define LL     2
#define E_UI   500000
#define E_TR   600000
#define E_II   400000
#define BB     512
#define KK     100
#define EPSV   1e-8f
#define ROWB   256               // byte stride of a dense [N,64] fp32 row

// CSR bins: user merged, train, ig0, ig1
#define NTOT   125000
#define ETOT   2400000
#define DBU 0
#define DB2 50000
#define DB3 75000
#define DB4 100000
#define EBT 0
#define EBI0 (E_TR)
#define EBI1 (E_TR + E_II)

// ---------------- device scratch (dense [N,64] per-layer tables) ----------
__device__ __align__(16) float g_U1[U_NN * DD];
__device__ __align__(16) float g_U2[U_NN * DD];
__device__ __align__(16) float g_I1[I_NN * DD];
__device__ __align__(16) float g_I2[I_NN * DD];
__device__ __align__(16) float g_S1[RR][I_NN * DD];
__device__ __align__(16) float g_S2[RR][I_NN * DD];
__device__ __align__(16) float g_Uagg[U_NN * DD];
__device__ __align__(16) float g_Iagg[I_NN * DD];
__device__ __align__(16) float g_IGagg[RR][I_NN * DD];
__device__            float g_cuser[U_NN * RR];
__device__            float g_invig[RR][I_NN];
__device__            float g_invdeg[I_NN];
__device__            int   g_cnt[NTOT];      // INVARIANT: zero at kernel_launch entry
__device__            int   g_off[NTOT];
__device__            int   g_cur[NTOT];
__device__ __align__(16) int g_edgeU[2 * E_UI];           // byteoff | r<<31
__device__ __align__(16) int g_srcA[E_TR + 2 * E_II];     // premultiplied byte offsets
__device__ __align__(16) float g_G[RR][DT * DT];
__device__ __align__(16) float g_z[RR][BB * DT];

#define ADDX2(d, a, b) asm("add.rn.f32x2 %0, %1, %2;" : "=l"(d) : "l"(a), "l"(b))
#define FMA2(d, a, b)  asm("fma.rn.f32x2 %0, %1, %2, %0;" : "+l"(d) : "l"(a), "l"(b))

// ---------------- launch 1: coeffs + histogram ----------------
__global__ void k_init_hist(const int* __restrict__ ubd, const int* __restrict__ igd,
                            const float* __restrict__ mgnn,
                            const int* __restrict__ rel_r, const int* __restrict__ tr_c,
                            const int* __restrict__ ig_r) {
    int t = blockIdx.x * blockDim.x + threadIdx.x;
    if (t < ETOT) {
        int d;
        if (t < 2 * E_UI)                    d = DBU + rel_r[t];
        else if (t < 2 * E_UI + E_TR)        d = DB2 + tr_c[t - 2 * E_UI];
        else if (t < 2 * E_UI + E_TR + E_II) d = DB3 + ig_r[t - (2 * E_UI + E_TR)];
        else                                 d = DB4 + ig_r[E_II + (t - (2 * E_UI + E_TR + E_II))];
        atomicAdd(&g_cnt[d], 1);
    }
    if (t < U_NN) {
        float m0 = mgnn[0], m1 = mgnn[1];
        float mx = fmaxf(m0, m1);
        float e0 = expf(m0 - mx), e1 = expf(m1 - mx);
        float inv = 1.0f / (e0 + e1);
        float w0 = e0 * inv, w1 = e1 * inv;
        float d0 = (float)ubd[t * 2 + 0], d1 = (float)ubd[t * 2 + 1];
        float itot = 1.0f / (d0 * w0 + d1 * w1 + EPSV);
        g_cuser[t * 2 + 0] = d0 * w0 * itot / (d0 + EPSV);
        g_cuser[t * 2 + 1] = d1 * w1 * itot / (d1 + EPSV);
    }
    if (t < I_NN) {
        g_invig[0][t] = 1.0f / ((float)igd[0 * I_NN + t] + EPSV);
        g_invig[1][t] = 1.0f / ((float)igd[1 * I_NN + t] + EPSV);
    }
}

// ---------------- launch 2: scan (offsets + cursors + invdeg) -------------
__global__ void k_scan() {
    __shared__ int sh[1024];
    const int DBv[4] = {DBU, DB2, DB3, DB4};
    const int DSv[4] = {U_NN, I_NN, I_NN, I_NN};
    int gsel = blockIdx.x;
    int base = DBv[gsel], size = DSv[gsel];
    int t = threadIdx.x;
    int chunk = (size + 1023) >> 10;
    int lo = t * chunk;
    int hi = lo + chunk; if (hi > size) hi = size;
    if (lo > size) lo = size;
    int s = 0;
    for (int i = lo; i < hi; i++) s += g_cnt[base + i];
    sh[t] = s;
    __syncthreads();
    for (int off = 1; off < 1024; off <<= 1) {
        int v = (t >= off) ? sh[t - off] : 0;
        __syncthreads();
        sh[t] += v;
        __syncthreads();
    }
    int run = (t > 0) ? sh[t - 1] : 0;
    for (int i = lo; i < hi; i++) {
        g_off[base + i] = run;
        g_cur[base + i] = run;
        run += g_cnt[base + i];
    }
    if (gsel == 1) {
        for (int i = lo; i < hi; i++)
            g_invdeg[i] = 1.0f / ((float)g_cnt[DB2 + i] + EPSV);
    }
}

// ---------------- launch 3: place (4B payload edges) ----------------------
__global__ void k_place_all(const int* __restrict__ rel_r, const int* __restrict__ rel_c,
                            const int* __restrict__ tr_r, const int* __restrict__ tr_c,
                            const int* __restrict__ ig_r, const int* __restrict__ ig_c) {
    int e = blockIdx.x * blockDim.x + threadIdx.x;
    if (e >= ETOT) return;
    if (e < 2 * E_UI) {
        int u = rel_r[e];
        int r = (e >= E_UI) ? 1 : 0;
        int off = rel_c[e] * ROWB | (r << 31);
        int p = atomicAdd(&g_cur[DBU + u], 1);
        g_edgeU[p] = off;
    } else if (e < 2 * E_UI + E_TR) {
        int j = e - 2 * E_UI;
        int p = atomicAdd(&g_cur[DB2 + tr_c[j]], 1);
        g_srcA[EBT + p] = tr_r[j] * ROWB;
    } else if (e < 2 * E_UI + E_TR + E_II) {
        int j = e - (2 * E_UI + E_TR);
        int p = atomicAdd(&g_cur[DB3 + ig_r[j]], 1);
        g_srcA[EBI0 + p] = ig_c[j] * ROWB;
    } else {
        int j = e - (2 * E_UI + E_TR + E_II);
        int p = atomicAdd(&g_cur[DB4 + ig_r[E_II + j]], 1);
        g_srcA[EBI1 + p] = ig_c[E_II + j] * ROWB;
    }
}

// ---------------- half-warp gathers: lane owns 4 columns ------------------
__device__ __forceinline__ float4 gather_half_w(const int* __restrict__ lst, int deg,
                                                const char* __restrict__ fb,
                                                float c0, float c1) {
    float4 a0 = {0.f,0.f,0.f,0.f}, a1 = {0.f,0.f,0.f,0.f};
    float4 a2 = {0.f,0.f,0.f,0.f}, a3 = {0.f,0.f,0.f,0.f};
    int j = 0;
    for (; j + 4 <= deg; j += 4) {
        int p0 = __ldg(lst + j + 0), p1 = __ldg(lst + j + 1);
        int p2 = __ldg(lst + j + 2), p3 = __ldg(lst + j + 3);
        float w0 = (p0 < 0) ? c1 : c0;
        float w1 = (p1 < 0) ? c1 : c0;
        float w2 = (p2 < 0) ? c1 : c0;
        float w3 = (p3 < 0) ? c1 : c0;
        float4 v0 = *reinterpret_cast<const float4*>(fb + (p0 & 0x7FFFFFFF));
        float4 v1 = *reinterpret_cast<const float4*>(fb + (p1 & 0x7FFFFFFF));
        float4 v2 = *reinterpret_cast<const float4*>(fb + (p2 & 0x7FFFFFFF));
        float4 v3 = *reinterpret_cast<const float4*>(fb + (p3 & 0x7FFFFFFF));
        a0.x += w0 * v0.x; a0.y += w0 * v0.y; a0.z += w0 * v0.z; a0.w += w0 * v0.w;
        a1.x += w1 * v1.x; a1.y += w1 * v1.y; a1.z += w1 * v1.z; a1.w += w1 * v1.w;
        a2.x += w2 * v2.x; a2.y += w2 * v2.y; a2.z += w2 * v2.z; a2.w += w2 * v2.w;
        a3.x += w3 * v3.x; a3.y += w3 * v3.y; a3.z += w3 * v3.z; a3.w += w3 * v3.w;
    }
    for (; j < deg; j++) {
        int p = __ldg(lst + j);
        float w = (p < 0) ? c1 : c0;
        float4 v = *reinterpret_cast<const float4*>(fb + (p & 0x7FFFFFFF));
        a0.x += w * v.x; a0.y += w * v.y; a0.z += w * v.z; a0.w += w * v.w;
    }
    a0.x += a1.x + a2.x + a3.x;
    a0.y += a1.y + a2.y + a3.y;
    a0.z += a1.z + a2.z + a3.z;
    a0.w += a1.w + a2.w + a3.w;
    return a0;
}

__device__ __forceinline__ float4 gather_half_u(const int* __restrict__ lst, int deg,
                                                const char* __restrict__ fb) {
    unsigned long long l0 = 0ull, h0 = 0ull, l1 = 0ull, h1 = 0ull;
    unsigned long long l2 = 0ull, h2 = 0ull, l3 = 0ull, h3 = 0ull;
    int j = 0;
    for (; j + 4 <= deg; j += 4) {
        int p0 = __ldg(lst + j + 0), p1 = __ldg(lst + j + 1);
        int p2 = __ldg(lst + j + 2), p3 = __ldg(lst + j + 3);
        ulonglong2 v0 = *reinterpret_cast<const ulonglong2*>(fb + p0);
        ulonglong2 v1 = *reinterpret_cast<const ulonglong2*>(fb + p1);
        ulonglong2 v2 = *reinterpret_cast<const ulonglong2*>(fb + p2);
        ulonglong2 v3 = *reinterpret_cast<const ulonglong2*>(fb + p3);
        ADDX2(l0, l0, v0.x); ADDX2(h0, h0, v0.y);
        ADDX2(l1, l1, v1.x); ADDX2(h1, h1, v1.y);
        ADDX2(l2, l2, v2.x); ADDX2(h2, h2, v2.y);
        ADDX2(l3, l3, v3.x); ADDX2(h3, h3, v3.y);
    }
    for (; j < deg; j++) {
        int p = __ldg(lst + j);
        ulonglong2 v = *reinterpret_cast<const ulonglong2*>(fb + p);
        ADDX2(l0, l0, v.x); ADDX2(h0, h0, v.y);
    }
    ADDX2(l0, l0, l1); ADDX2(l2, l2, l3); ADDX2(l0, l0, l2);
    ADDX2(h0, h0, h1); ADDX2(h2, h2, h3); ADDX2(h0, h0, h2);
    float4 r;
    r.x = __uint_as_float((unsigned)(l0 & 0xFFFFFFFFull));
    r.y = __uint_as_float((unsigned)(l0 >> 32));
    r.z = __uint_as_float((unsigned)(h0 & 0xFFFFFFFFull));
    r.w = __uint_as_float((unsigned)(h0 >> 32));
    return r;
}

// ---------------- launch 4/6: fused gather (half-warp per destination) ----
__global__ void __launch_bounds__(256, 5) k_gather_all(const float* __restrict__ uSrc,
                                                       const float* __restrict__ iSrc) {
    int hw = (blockIdx.x * blockDim.x + threadIdx.x) >> 4;
    if (hw >= U_NN + 3 * I_NN) return;
    int hl = threadIdx.x & 15;
    float4 r;
    float* dst;
    int row;
    if (hw < U_NN) {
        float c0 = g_cuser[hw * 2 + 0], c1 = g_cuser[hw * 2 + 1];
        r = gather_half_w(g_edgeU + g_off[DBU + hw], g_cnt[DBU + hw],
                          (const char*)iSrc + hl * 16, c0, c1);
        dst = g_Uagg; row = hw;
    } else {
        int v = hw - U_NN;
        int gsel = v / I_NN;
        int i = v - gsel * I_NN;
        float4 a; float c;
        if (gsel == 0) {
            a = gather_half_u(g_srcA + EBT + g_off[DB2 + i], g_cnt[DB2 + i],
                              (const char*)uSrc + hl * 16);
            c = g_invdeg[i]; dst = g_Iagg;
        } else if (gsel == 1) {
            a = gather_half_u(g_srcA + EBI0 + g_off[DB3 + i], g_cnt[DB3 + i],
                              (const char*)iSrc + hl * 16);
            c = g_invig[0][i]; dst = g_IGagg[0];
        } else {
            a = gather_half_u(g_srcA + EBI1 + g_off[DB4 + i], g_cnt[DB4 + i],
                              (const char*)iSrc + hl * 16);
            c = g_invig[1][i]; dst = g_IGagg[1];
        }
        r = make_float4(a.x * c, a.y * c, a.z * c, a.w * c);
        row = i;
    }
    *reinterpret_cast<float4*>(&dst[(long)row * DD + hl * 4]) = r;
}

// ---------------- launch 5/7: fused dense projections (FFMA2 path) --------
// Row-pair-packed accumulators; W staged duplicated in smem as (w,w) pairs,
// in two 32-k halves to bound smem at ~34KB.
__global__ void k_gemm_all(const float* __restrict__ W_ui_l,
                           const float* __restrict__ W_ii0_l,
                           const float* __restrict__ W_ii1_l,
                           float* __restrict__ Udst, float* __restrict__ Idst,
                           float* __restrict__ S0dst, float* __restrict__ S1dst) {
    __shared__ __align__(16) float As[64 * 68];       // [k][row], padded
    __shared__ __align__(16) float Wd[32 * 64 * 2];   // (w,w) pairs, one 32-k half
    int sel = blockIdx.y;
    const float* src; float* dst; const float* W; int N;
    if (sel == 0)      { src = g_Uagg;     dst = Udst;  W = W_ui_l;  N = U_NN; }
    else if (sel == 1) { src = g_Iagg;     dst = Idst;  W = W_ui_l;  N = I_NN; }
    else if (sel == 2) { src = g_IGagg[0]; dst = S0dst; W = W_ii0_l; N = I_NN; }
    else               { src = g_IGagg[1]; dst = S1dst; W = W_ii1_l; N = I_NN; }
    int row0 = blockIdx.x * 64;
    if (row0 >= N) return;
    int tid = threadIdx.x;

    for (int i = tid; i < 4096; i += 256) {
        int rr = i >> 6, k = i & 63;
        float v = (row0 + rr < N) ? src[(long)(row0 + rr) * DD + k] : 0.f;
        As[k * 68 + rr] = v;
    }

    int cg = tid & 15, rg = tid >> 4;
    // acc[ip][j]: packed rows (rg*4+2ip, rg*4+2ip+1), column cg*4+j
    unsigned long long acc[2][4];
#pragma unroll
    for (int i = 0; i < 2; i++)
#pragma unroll
        for (int j = 0; j < 4; j++) acc[i][j] = 0ull;

    for (int half = 0; half < 2; half++) {
        __syncthreads();   // As ready (half 0) / prior readers done (half 1)
        for (int i = tid; i < 2048; i += 256) {
            float w = W[half * 2048 + i];          // i = kk*64 + j
            Wd[i * 2] = w; Wd[i * 2 + 1] = w;
        }
        __syncthreads();
#pragma unroll 8
        for (int kk = 0; kk < 32; kk++) {
            int k = half * 32 + kk;
            float4 a4 = *reinterpret_cast<const float4*>(&As[k * 68 + rg * 4]);
            ulonglong2 ap = *reinterpret_cast<ulonglong2*>(&a4); // (r0,r1),(r2,r3)
            const ulonglong2* wp = reinterpret_cast<const ulonglong2*>(
                &Wd[(kk * 64 + cg * 4) * 2]);
            ulonglong2 q0 = wp[0];   // (w0,w0),(w1,w1)
            ulonglong2 q1 = wp[1];   // (w2,w2),(w3,w3)
            FMA2(acc[0][0], ap.x, q0.x); FMA2(acc[1][0], ap.y, q0.x);
            FMA2(acc[0][1], ap.x, q0.y); FMA2(acc[1][1], ap.y, q0.y);
            FMA2(acc[0][2], ap.x, q1.x); FMA2(acc[1][2], ap.y, q1.x);
            FMA2(acc[0][3], ap.x, q1.y); FMA2(acc[1][3], ap.y, q1.y);
        }
    }

#pragma unroll
    for (int i = 0; i < 4; i++) {
        int row = row0 + rg * 4 + i;
        if (row < N) {
            int ip = i >> 1;
            int hi = i & 1;
            float4 o;
            o.x = __uint_as_float(hi ? (unsigned)(acc[ip][0] >> 32) : (unsigned)acc[ip][0]);
            o.y = __uint_as_float(hi ? (unsigned)(acc[ip][1] >> 32) : (unsigned)acc[ip][1]);
            o.z = __uint_as_float(hi ? (unsigned)(acc[ip][2] >> 32) : (unsigned)acc[ip][2]);
            o.w = __uint_as_float(hi ? (unsigned)(acc[ip][3] >> 32) : (unsigned)acc[ip][3]);
            *reinterpret_cast<float4*>(&dst[(long)row * DD + cg * 4]) = o;
        }
    }
}

// ---------------- scoring ----------------
__global__ void k_G(const float* __restrict__ bW, float* out, int lossIdx) {
    __shared__ float Asm[32 * 192];
    __shared__ float Bsm[32 * 192];
    if (blockIdx.x == 0 && blockIdx.y == 0 && blockIdx.z == 0 && threadIdx.x == 0)
        out[lossIdx] = 0.f;
    int r = blockIdx.z;
    const float* W = bW + (long)r * DT * DT;
    int i0 = blockIdx.x * 32, j0 = blockIdx.y * 32;
    for (int t = threadIdx.x; t < 32 * 192; t += 256) {
        Asm[t] = W[(long)(i0 + t / 192) * DT + (t % 192)];
        Bsm[t] = W[(long)(j0 + t / 192) * DT + (t % 192)];
    }
    __syncthreads();
    int tj = threadIdx.x & 15, ti = threadIdx.x >> 4;
    float acc[2][2] = {{0.f, 0.f}, {0.f, 0.f}};
    for (int k = 0; k < 192; k++) {
        float a0 = Asm[(ti * 2 + 0) * 192 + k];
        float a1 = Asm[(ti * 2 + 1) * 192 + k];
        float b0 = Bsm[(tj * 2 + 0) * 192 + k];
        float b1 = Bsm[(tj * 2 + 1) * 192 + k];
        acc[0][0] += a0 * b0; acc[0][1] += a0 * b1;
        acc[1][0] += a1 * b0; acc[1][1] += a1 * b1;
    }
#pragma unroll
    for (int i = 0; i < 2; i++)
#pragma unroll
        for (int j = 0; j < 2; j++)
            g_G[r][(long)(i0 + ti * 2 + i) * DT + (j0 + tj * 2 + j)] = acc[i][j];
}

// block per (b,r): aggregate batched user's rel-r subset (sign bit = r), z = agg @ G
__global__ void k_aggsel_z(const int* __restrict__ users, const int* __restrict__ ubd,
                           const float* __restrict__ ie) {
    __shared__ float as[DT];
    int b = blockIdx.x, r = blockIdx.y, c = threadIdx.x;
    int u = users[b];
    const int* lst = g_edgeU + g_off[DBU + u];
    int deg = g_cnt[DBU + u];
    const float* T = (c < 64) ? ie : (c < 128) ? g_S1[r] : g_S2[r];
    const char* Tb = (const char*)T + (c & 63) * 4;
    float a0 = 0.f;
    for (int j = 0; j < deg; j++) {
        int p = __ldg(&lst[j]);
        int er = (p < 0) ? 1 : 0;
        if (er == r)
            a0 += *reinterpret_cast<const float*>(Tb + (p & 0x7FFFFFFF));
    }
    float coeff = 1.0f / ((float)ubd[u * 2 + r] + EPSV);
    as[c] = a0 * coeff;
    __syncthreads();
    float acc = 0.f;
    const float* G = g_G[r];
#pragma unroll 4
    for (int k = 0; k < DT; k++) acc += as[k] * G[(long)k * DT + c];
    g_z[r][(long)b * DT + c] = acc;
}

// warp per (b,k); restores g_cnt==0 invariant
__global__ void k_score(const int* __restrict__ users, const int* __restrict__ items,
                        const float* __restrict__ ue, const float* __restrict__ ie,
                        float* out, int lossIdx) {
    __shared__ float l2blk;
    int tg = blockIdx.x * blockDim.x + threadIdx.x;
    if (tg < NTOT) g_cnt[tg] = 0;
    if (threadIdx.x == 0) l2blk = 0.f;
    __syncthreads();
    int w = tg >> 5;
    int lane = threadIdx.x & 31;
    if (w < BB * KK) {
        int b = w / KK;
        int kk = w - b * KK;
        int u = users[b];
        int it = items[w];
        float s1 = 0.f, s2a = 0.f, s2b = 0.f, l2i = 0.f, l2u = 0.f;
        const float* z0 = g_z[0] + (long)b * DT;
        const float* z1 = g_z[1] + (long)b * DT;
#pragma unroll
        for (int s = 0; s < 2; s++) {
            int c = lane + 32 * s;
            {
                float bu = ue[(long)u * DD + c];
                float bi = ie[(long)it * DD + c];
                s1 += bu * bi; l2i += bi * bi;
                if (kk == 0) l2u += bu * bu;
                s2a += z0[c] * bi;
                s2b += z1[c] * bi;
            }
            {
                float bu = g_U1[(long)u * DD + c];
                float bi = g_I1[(long)it * DD + c];
                s1 += bu * bi; l2i += bi * bi;
                if (kk == 0) l2u += bu * bu;
                s2a += z0[64 + c] * g_S1[0][(long)it * DD + c];
                s2b += z1[64 + c] * g_S1[1][(long)it * DD + c];
            }
            {
                float bu = g_U2[(long)u * DD + c];
                float bi = g_I2[(long)it * DD + c];
                s1 += bu * bi; l2i += bi * bi;
                if (kk == 0) l2u += bu * bu;
                s2a += z0[128 + c] * g_S2[0][(long)it * DD + c];
                s2b += z1[128 + c] * g_S2[1][(long)it * DD + c];
            }
        }
#pragma unroll
        for (int off = 16; off; off >>= 1) {
            s1  += __shfl_down_sync(0xffffffffu, s1, off);
            s2a += __shfl_down_sync(0xffffffffu, s2a, off);
            s2b += __shfl_down_sync(0xffffffffu, s2b, off);
            l2i += __shfl_down_sync(0xffffffffu, l2i, off);
            if (kk == 0) l2u += __shfl_down_sync(0xffffffffu, l2u, off);
        }
        if (lane == 0) {
            out[w] = 0.5f * s1 + 0.25f * (s2a + s2b);
            atomicAdd(&l2blk, l2i + (kk == 0 ? (float)KK * l2u : 0.f));
        }
    }
    __syncthreads();
    if (threadIdx.x == 0) atomicAdd(out + lossIdx, 1e-4f * l2blk);
}

// ---------------- launch ----------------
extern "C" void kernel_launch(void* const* d_in, const int* in_sizes, int n_in,
                              void* d_out, int out_size) {
    const float* ue    = (const float*)d_in[0];
    const float* ie    = (const float*)d_in[1];
    const float* W_ui  = (const float*)d_in[2];
    const float* W_ii  = (const float*)d_in[3];
    const float* bW    = (const float*)d_in[4];
    const float* mgnn  = (const float*)d_in[5];
    const int* rel_r   = (const int*)d_in[6];
    const int* rel_c   = (const int*)d_in[7];
    const int* tr_r    = (const int*)d_in[8];
    const int* tr_c    = (const int*)d_in[9];
    const int* ig_r    = (const int*)d_in[10];
    const int* ig_c    = (const int*)d_in[11];
    const int* ubd     = (const int*)d_in[12];
    const int* igd     = (const int*)d_in[13];
    const int* users   = (const int*)d_in[14];
    const int* items   = (const int*)d_in[15];
    float* out = (float*)d_out;
    int lossIdx = out_size - 1;

    const int T = 256;
    auto g = [](long n, int t) { return (int)((n + t - 1) / t); };

    float *U1, *U2, *I1, *I2, *S10, *S11, *S20, *S21;
    cudaGetSymbolAddress((void**)&U1,  g_U1);
    cudaGetSymbolAddress((void**)&U2,  g_U2);
    cudaGetSymbolAddress((void**)&I1,  g_I1);
    cudaGetSymbolAddress((void**)&I2,  g_I2);
    cudaGetSymbolAddress((void**)&S10, g_S1);
    cudaGetSymbolAddress((void**)&S20, g_S2);
    S11 = S10 + I_NN * DD;
    S21 = S20 + I_NN * DD;

    // 1-3: init + CSR build
    k_init_hist<<<g(ETOT, T), T>>>(ubd, igd, mgnn, rel_r, tr_c, ig_r);
    k_scan<<<4, 1024>>>();
    k_place_all<<<g(ETOT, T), T>>>(rel_r, rel_c, tr_r, tr_c, ig_r, ig_c);

    // 4-7: two propagation layers (layer-0 tables ARE the inputs)
    {
        dim3 gg(g(U_NN, 64), 4);
        k_gather_all<<<g((long)(U_NN + 3 * I_NN) * 16, T), T>>>(ue, ie);
        k_gemm_all<<<gg, 256>>>(W_ui, W_ii, W_ii + (long)LL * DD * DD,
                                U1, I1, S10, S11);
        k_gather_all<<<g((long)(U_NN + 3 * I_NN) * 16, T), T>>>(U1, I1);
        k_gemm_all<<<gg, 256>>>(W_ui + (long)DD * DD,
                                W_ii + (long)DD * DD,
                                W_ii + (long)(LL + 1) * DD * DD,
                                U2, I2, S20, S21);
    }

    // 8-10: scoring
    {
        dim3 ggG(6, 6, 2);
        k_G<<<ggG, 256>>>(bW, out, lossIdx);
    }
    {
        dim3 gz(BB, RR);
        k_aggsel_z<<<gz, DT>>>(users, ubd, ie);
    }
    k_score<<<g((long)BB * KK * 32, T), T>>>(users, items, ue, ie, out, lossIdx);
}

// round 16
// speedup vs baseline: 1.1838x; 1.1838x over previous
#include <cuda_runtime.h>
#include <cuda_bf16.h>
#include <math.h>

// ---------------- problem constants ----------------
#define U_NN   50000
#define I_NN   25000
#define DD     64
#define DT     192
#define RR     2
#define LL     2
#define E_UI   500000
#define E_TR   600000
#define E_II   400000
#define BB     512
#define KK     100
#define EPSV   1e-8f
#define ROWB   256               // byte stride of a dense [N,64] fp32 row

// CSR bins: user merged, train, ig0, ig1
#define NTOT   125000
#define ETOT   2400000
#define DBU 0
#define DB2 50000
#define DB3 75000
#define DB4 100000
#define EBT 0
#define EBI0 (E_TR)
#define EBI1 (E_TR + E_II)

// ---------------- device scratch (dense [N,64] per-layer tables) ----------
__device__ __align__(16) float g_U1[U_NN * DD];
__device__ __align__(16) float g_U2[U_NN * DD];
__device__ __align__(16) float g_I1[I_NN * DD];
__device__ __align__(16) float g_I2[I_NN * DD];
__device__ __align__(16) float g_S1[RR][I_NN * DD];
__device__ __align__(16) float g_S2[RR][I_NN * DD];
__device__ __align__(16) float g_Uagg[U_NN * DD];
__device__ __align__(16) float g_Iagg[I_NN * DD];
__device__ __align__(16) float g_IGagg[RR][I_NN * DD];
__device__            float g_cuser[U_NN * RR];
__device__            float g_invig[RR][I_NN];
__device__            float g_invdeg[I_NN];
__device__            int   g_cnt[NTOT];      // INVARIANT: zero at kernel_launch entry
__device__            int   g_off[NTOT];
__device__            int   g_cur[NTOT];
__device__ __align__(16) int g_edgeU[2 * E_UI];           // byteoff | r<<31
__device__ __align__(16) int g_srcA[E_TR + 2 * E_II];     // premultiplied byte offsets
__device__ __align__(16) float g_G[RR][DT * DT];
__device__ __align__(16) float g_z[RR][BB * DT];

#define ADDX2(d, a, b) asm("add.rn.f32x2 %0, %1, %2;" : "=l"(d) : "l"(a), "l"(b))

// ---------------- launch 1: coeffs + histogram ----------------
__global__ void k_init_hist(const int* __restrict__ ubd, const int* __restrict__ igd,
                            const float* __restrict__ mgnn,
                            const int* __restrict__ rel_r, const int* __restrict__ tr_c,
                            const int* __restrict__ ig_r) {
    int t = blockIdx.x * blockDim.x + threadIdx.x;
    if (t < ETOT) {
        int d;
        if (t < 2 * E_UI)                    d = DBU + rel_r[t];
        else if (t < 2 * E_UI + E_TR)        d = DB2 + tr_c[t - 2 * E_UI];
        else if (t < 2 * E_UI + E_TR + E_II) d = DB3 + ig_r[t - (2 * E_UI + E_TR)];
        else                                 d = DB4 + ig_r[E_II + (t - (2 * E_UI + E_TR + E_II))];
        atomicAdd(&g_cnt[d], 1);
    }
    if (t < U_NN) {
        float m0 = mgnn[0], m1 = mgnn[1];
        float mx = fmaxf(m0, m1);
        float e0 = expf(m0 - mx), e1 = expf(m1 - mx);
        float inv = 1.0f / (e0 + e1);
        float w0 = e0 * inv, w1 = e1 * inv;
        float d0 = (float)ubd[t * 2 + 0], d1 = (float)ubd[t * 2 + 1];
        float itot = 1.0f / (d0 * w0 + d1 * w1 + EPSV);
        g_cuser[t * 2 + 0] = d0 * w0 * itot / (d0 + EPSV);
        g_cuser[t * 2 + 1] = d1 * w1 * itot / (d1 + EPSV);
    }
    if (t < I_NN) {
        g_invig[0][t] = 1.0f / ((float)igd[0 * I_NN + t] + EPSV);
        g_invig[1][t] = 1.0f / ((float)igd[1 * I_NN + t] + EPSV);
    }
}

// ---------------- launch 2: scan (offsets + cursors + invdeg) -------------
__global__ void k_scan() {
    __shared__ int sh[1024];
    const int DBv[4] = {DBU, DB2, DB3, DB4};
    const int DSv[4] = {U_NN, I_NN, I_NN, I_NN};
    int gsel = blockIdx.x;
    int base = DBv[gsel], size = DSv[gsel];
    int t = threadIdx.x;
    int chunk = (size + 1023) >> 10;
    int lo = t * chunk;
    int hi = lo + chunk; if (hi > size) hi = size;
    if (lo > size) lo = size;
    int s = 0;
    for (int i = lo; i < hi; i++) s += g_cnt[base + i];
    sh[t] = s;
    __syncthreads();
    for (int off = 1; off < 1024; off <<= 1) {
        int v = (t >= off) ? sh[t - off] : 0;
        __syncthreads();
        sh[t] += v;
        __syncthreads();
    }
    int run = (t > 0) ? sh[t - 1] : 0;
    for (int i = lo; i < hi; i++) {
        g_off[base + i] = run;
        g_cur[base + i] = run;
        run += g_cnt[base + i];
    }
    if (gsel == 1) {
        for (int i = lo; i < hi; i++)
            g_invdeg[i] = 1.0f / ((float)g_cnt[DB2 + i] + EPSV);
    }
}

// ---------------- launch 3: place (4B payload edges) ----------------------
__global__ void k_place_all(const int* __restrict__ rel_r, const int* __restrict__ rel_c,
                            const int* __restrict__ tr_r, const int* __restrict__ tr_c,
                            const int* __restrict__ ig_r, const int* __restrict__ ig_c) {
    int e = blockIdx.x * blockDim.x + threadIdx.x;
    if (e >= ETOT) return;
    if (e < 2 * E_UI) {
        int u = rel_r[e];
        int r = (e >= E_UI) ? 1 : 0;
        int off = rel_c[e] * ROWB | (r << 31);
        int p = atomicAdd(&g_cur[DBU + u], 1);
        g_edgeU[p] = off;
    } else if (e < 2 * E_UI + E_TR) {
        int j = e - 2 * E_UI;
        int p = atomicAdd(&g_cur[DB2 + tr_c[j]], 1);
        g_srcA[EBT + p] = tr_r[j] * ROWB;
    } else if (e < 2 * E_UI + E_TR + E_II) {
        int j = e - (2 * E_UI + E_TR);
        int p = atomicAdd(&g_cur[DB3 + ig_r[j]], 1);
        g_srcA[EBI0 + p] = ig_c[j] * ROWB;
    } else {
        int j = e - (2 * E_UI + E_TR + E_II);
        int p = atomicAdd(&g_cur[DB4 + ig_r[E_II + j]], 1);
        g_srcA[EBI1 + p] = ig_c[E_II + j] * ROWB;
    }
}

// ---------------- half-warp gathers: lane owns 4 columns ------------------
// fb = table byte base + 16*(lane&15); entries carry byte offsets.
// Software-pipelined: next quad's indices prefetched during current quad.
__device__ __forceinline__ float4 gather_half_w(const int* __restrict__ lst, int deg,
                                                const char* __restrict__ fb,
                                                float c0, float c1) {
    float4 a0 = {0.f,0.f,0.f,0.f}, a1 = {0.f,0.f,0.f,0.f};
    float4 a2 = {0.f,0.f,0.f,0.f}, a3 = {0.f,0.f,0.f,0.f};
    int j = 0;
    if (deg >= 4) {
        int p0 = __ldg(lst + 0), p1 = __ldg(lst + 1);
        int p2 = __ldg(lst + 2), p3 = __ldg(lst + 3);
        for (; j + 8 <= deg; j += 4) {
            int n0 = __ldg(lst + j + 4), n1 = __ldg(lst + j + 5);
            int n2 = __ldg(lst + j + 6), n3 = __ldg(lst + j + 7);
            float w0 = (p0 < 0) ? c1 : c0;
            float w1 = (p1 < 0) ? c1 : c0;
            float w2 = (p2 < 0) ? c1 : c0;
            float w3 = (p3 < 0) ? c1 : c0;
            float4 v0 = *reinterpret_cast<const float4*>(fb + (p0 & 0x7FFFFFFF));
            float4 v1 = *reinterpret_cast<const float4*>(fb + (p1 & 0x7FFFFFFF));
            float4 v2 = *reinterpret_cast<const float4*>(fb + (p2 & 0x7FFFFFFF));
            float4 v3 = *reinterpret_cast<const float4*>(fb + (p3 & 0x7FFFFFFF));
            a0.x += w0 * v0.x; a0.y += w0 * v0.y; a0.z += w0 * v0.z; a0.w += w0 * v0.w;
            a1.x += w1 * v1.x; a1.y += w1 * v1.y; a1.z += w1 * v1.z; a1.w += w1 * v1.w;
            a2.x += w2 * v2.x; a2.y += w2 * v2.y; a2.z += w2 * v2.z; a2.w += w2 * v2.w;
            a3.x += w3 * v3.x; a3.y += w3 * v3.y; a3.z += w3 * v3.z; a3.w += w3 * v3.w;
            p0 = n0; p1 = n1; p2 = n2; p3 = n3;
        }
        {   // drain the in-flight quad (j .. j+3 valid)
            float w0 = (p0 < 0) ? c1 : c0;
            float w1 = (p1 < 0) ? c1 : c0;
            float w2 = (p2 < 0) ? c1 : c0;
            float w3 = (p3 < 0) ? c1 : c0;
            float4 v0 = *reinterpret_cast<const float4*>(fb + (p0 & 0x7FFFFFFF));
            float4 v1 = *reinterpret_cast<const float4*>(fb + (p1 & 0x7FFFFFFF));
            float4 v2 = *reinterpret_cast<const float4*>(fb + (p2 & 0x7FFFFFFF));
            float4 v3 = *reinterpret_cast<const float4*>(fb + (p3 & 0x7FFFFFFF));
            a0.x += w0 * v0.x; a0.y += w0 * v0.y; a0.z += w0 * v0.z; a0.w += w0 * v0.w;
            a1.x += w1 * v1.x; a1.y += w1 * v1.y; a1.z += w1 * v1.z; a1.w += w1 * v1.w;
            a2.x += w2 * v2.x; a2.y += w2 * v2.y; a2.z += w2 * v2.z; a2.w += w2 * v2.w;
            a3.x += w3 * v3.x; a3.y += w3 * v3.y; a3.z += w3 * v3.z; a3.w += w3 * v3.w;
            j += 4;
        }
    }
    for (; j < deg; j++) {
        int p = __ldg(lst + j);
        float w = (p < 0) ? c1 : c0;
        float4 v = *reinterpret_cast<const float4*>(fb + (p & 0x7FFFFFFF));
        a0.x += w * v.x; a0.y += w * v.y; a0.z += w * v.z; a0.w += w * v.w;
    }
    a0.x += a1.x + a2.x + a3.x;
    a0.y += a1.y + a2.y + a3.y;
    a0.z += a1.z + a2.z + a3.z;
    a0.w += a1.w + a2.w + a3.w;
    return a0;
}

// Unweighted: packed f32x2 adds; same index software-pipeline.
__device__ __forceinline__ float4 gather_half_u(const int* __restrict__ lst, int deg,
                                                const char* __restrict__ fb) {
    unsigned long long l0 = 0ull, h0 = 0ull, l1 = 0ull, h1 = 0ull;
    unsigned long long l2 = 0ull, h2 = 0ull, l3 = 0ull, h3 = 0ull;
    int j = 0;
    if (deg >= 4) {
        int p0 = __ldg(lst + 0), p1 = __ldg(lst + 1);
        int p2 = __ldg(lst + 2), p3 = __ldg(lst + 3);
        for (; j + 8 <= deg; j += 4) {
            int n0 = __ldg(lst + j + 4), n1 = __ldg(lst + j + 5);
            int n2 = __ldg(lst + j + 6), n3 = __ldg(lst + j + 7);
            ulonglong2 v0 = *reinterpret_cast<const ulonglong2*>(fb + p0);
            ulonglong2 v1 = *reinterpret_cast<const ulonglong2*>(fb + p1);
            ulonglong2 v2 = *reinterpret_cast<const ulonglong2*>(fb + p2);
            ulonglong2 v3 = *reinterpret_cast<const ulonglong2*>(fb + p3);
            ADDX2(l0, l0, v0.x); ADDX2(h0, h0, v0.y);
            ADDX2(l1, l1, v1.x); ADDX2(h1, h1, v1.y);
            ADDX2(l2, l2, v2.x); ADDX2(h2, h2, v2.y);
            ADDX2(l3, l3, v3.x); ADDX2(h3, h3, v3.y);
            p0 = n0; p1 = n1; p2 = n2; p3 = n3;
        }
        {
            ulonglong2 v0 = *reinterpret_cast<const ulonglong2*>(fb + p0);
            ulonglong2 v1 = *reinterpret_cast<const ulonglong2*>(fb + p1);
            ulonglong2 v2 = *reinterpret_cast<const ulonglong2*>(fb + p2);
            ulonglong2 v3 = *reinterpret_cast<const ulonglong2*>(fb + p3);
            ADDX2(l0, l0, v0.x); ADDX2(h0, h0, v0.y);
            ADDX2(l1, l1, v1.x); ADDX2(h1, h1, v1.y);
            ADDX2(l2, l2, v2.x); ADDX2(h2, h2, v2.y);
            ADDX2(l3, l3, v3.x); ADDX2(h3, h3, v3.y);
            j += 4;
        }
    }
    for (; j < deg; j++) {
        int p = __ldg(lst + j);
        ulonglong2 v = *reinterpret_cast<const ulonglong2*>(fb + p);
        ADDX2(l0, l0, v.x); ADDX2(h0, h0, v.y);
    }
    ADDX2(l0, l0, l1); ADDX2(l2, l2, l3); ADDX2(l0, l0, l2);
    ADDX2(h0, h0, h1); ADDX2(h2, h2, h3); ADDX2(h0, h0, h2);
    float4 r;
    r.x = __uint_as_float((unsigned)(l0 & 0xFFFFFFFFull));
    r.y = __uint_as_float((unsigned)(l0 >> 32));
    r.z = __uint_as_float((unsigned)(h0 & 0xFFFFFFFFull));
    r.w = __uint_as_float((unsigned)(h0 >> 32));
    return r;
}

// ---------------- launch 4/6: fused gather (half-warp per destination) ----
__global__ void __launch_bounds__(256, 5) k_gather_all(const float* __restrict__ uSrc,
                                                       const float* __restrict__ iSrc) {
    int hw = (blockIdx.x * blockDim.x + threadIdx.x) >> 4;
    if (hw >= U_NN + 3 * I_NN) return;
    int hl = threadIdx.x & 15;
    float4 r;
    float* dst;
    int row;
    if (hw < U_NN) {
        float c0 = g_cuser[hw * 2 + 0], c1 = g_cuser[hw * 2 + 1];
        r = gather_half_w(g_edgeU + g_off[DBU + hw], g_cnt[DBU + hw],
                          (const char*)iSrc + hl * 16, c0, c1);
        dst = g_Uagg; row = hw;
    } else {
        int v = hw - U_NN;
        int gsel = v / I_NN;
        int i = v - gsel * I_NN;
        float4 a; float c;
        if (gsel == 0) {
            a = gather_half_u(g_srcA + EBT + g_off[DB2 + i], g_cnt[DB2 + i],
                              (const char*)uSrc + hl * 16);
            c = g_invdeg[i]; dst = g_Iagg;
        } else if (gsel == 1) {
            a = gather_half_u(g_srcA + EBI0 + g_off[DB3 + i], g_cnt[DB3 + i],
                              (const char*)iSrc + hl * 16);
            c = g_invig[0][i]; dst = g_IGagg[0];
        } else {
            a = gather_half_u(g_srcA + EBI1 + g_off[DB4 + i], g_cnt[DB4 + i],
                              (const char*)iSrc + hl * 16);
            c = g_invig[1][i]; dst = g_IGagg[1];
        }
        r = make_float4(a.x * c, a.y * c, a.z * c, a.w * c);
        row = i;
    }
    *reinterpret_cast<float4*>(&dst[(long)row * DD + hl * 4]) = r;
}

// ---------------- launch 5/7: fused dense projections (R10 version) -------
__global__ void k_gemm_all(const float* __restrict__ W_ui_l,
                           const float* __restrict__ W_ii0_l,
                           const float* __restrict__ W_ii1_l,
                           float* __restrict__ Udst, float* __restrict__ Idst,
                           float* __restrict__ S0dst, float* __restrict__ S1dst) {
    __shared__ __align__(16) float Ws[64 * 64];
    __shared__ __align__(16) float As[64 * 68];
    int sel = blockIdx.y;
    const float* src; float* dst; const float* W; int N;
    if (sel == 0)      { src = g_Uagg;     dst = Udst;  W = W_ui_l;  N = U_NN; }
    else if (sel == 1) { src = g_Iagg;     dst = Idst;  W = W_ui_l;  N = I_NN; }
    else if (sel == 2) { src = g_IGagg[0]; dst = S0dst; W = W_ii0_l; N = I_NN; }
    else               { src = g_IGagg[1]; dst = S1dst; W = W_ii1_l; N = I_NN; }
    int row0 = blockIdx.x * 64;
    if (row0 >= N) return;
    int tid = threadIdx.x;

    for (int i = tid; i < 4096; i += 256) Ws[i] = W[i];
    for (int i = tid; i < 4096; i += 256) {
        int rr = i >> 6, k = i & 63;
        float v = (row0 + rr < N) ? src[(long)(row0 + rr) * DD + k] : 0.f;
        As[k * 68 + rr] = v;
    }
    __syncthreads();

    int cg = tid & 15, rg = tid >> 4;
    float acc[4][4];
#pragma unroll
    for (int i = 0; i < 4; i++)
#pragma unroll
        for (int j = 0; j < 4; j++) acc[i][j] = 0.f;

#pragma unroll 8
    for (int k = 0; k < 64; k++) {
        float4 a4 = *reinterpret_cast<const float4*>(&As[k * 68 + rg * 4]);
        float4 w4 = *reinterpret_cast<const float4*>(&Ws[k * 64 + cg * 4]);
        float a[4] = {a4.x, a4.y, a4.z, a4.w};
        float w[4] = {w4.x, w4.y, w4.z, w4.w};
#pragma unroll
        for (int i = 0; i < 4; i++)
#pragma unroll
            for (int j = 0; j < 4; j++) acc[i][j] += a[i] * w[j];
    }
#pragma unroll
    for (int i = 0; i < 4; i++) {
        int row = row0 + rg * 4 + i;
        if (row < N) {
            float4 o = make_float4(acc[i][0], acc[i][1], acc[i][2], acc[i][3]);
            *reinterpret_cast<float4*>(&dst[(long)row * DD + cg * 4]) = o;
        }
    }
}

// ---------------- scoring ----------------
__global__ void k_G(const float* __restrict__ bW, float* out, int lossIdx) {
    __shared__ float Asm[32 * 192];
    __shared__ float Bsm[32 * 192];
    if (blockIdx.x == 0 && blockIdx.y == 0 && blockIdx.z == 0 && threadIdx.x == 0)
        out[lossIdx] = 0.f;
    int r = blockIdx.z;
    const float* W = bW + (long)r * DT * DT;
    int i0 = blockIdx.x * 32, j0 = blockIdx.y * 32;
    for (int t = threadIdx.x; t < 32 * 192; t += 256) {
        Asm[t] = W[(long)(i0 + t / 192) * DT + (t % 192)];
        Bsm[t] = W[(long)(j0 + t / 192) * DT + (t % 192)];
    }
    __syncthreads();
    int tj = threadIdx.x & 15, ti = threadIdx.x >> 4;
    float acc[2][2] = {{0.f, 0.f}, {0.f, 0.f}};
    for (int k = 0; k < 192; k++) {
        float a0 = Asm[(ti * 2 + 0) * 192 + k];
        float a1 = Asm[(ti * 2 + 1) * 192 + k];
        float b0 = Bsm[(tj * 2 + 0) * 192 + k];
        float b1 = Bsm[(tj * 2 + 1) * 192 + k];
        acc[0][0] += a0 * b0; acc[0][1] += a0 * b1;
        acc[1][0] += a1 * b0; acc[1][1] += a1 * b1;
    }
#pragma unroll
    for (int i = 0; i < 2; i++)
#pragma unroll
        for (int j = 0; j < 2; j++)
            g_G[r][(long)(i0 + ti * 2 + i) * DT + (j0 + tj * 2 + j)] = acc[i][j];
}

// block per (b,r): aggregate batched user's rel-r subset (sign bit = r), z = agg @ G
__global__ void k_aggsel_z(const int* __restrict__ users, const int* __restrict__ ubd,
                           const float* __restrict__ ie) {
    __shared__ float as[DT];
    int b = blockIdx.x, r = blockIdx.y, c = threadIdx.x;
    int u = users[b];
    const int* lst = g_edgeU + g_off[DBU + u];
    int deg = g_cnt[DBU + u];
    const float* T = (c < 64) ? ie : (c < 128) ? g_S1[r] : g_S2[r];
    const char* Tb = (const char*)T + (c & 63) * 4;
    float a0 = 0.f;
    for (int j = 0; j < deg; j++) {
        int p = __ldg(&lst[j]);
        int er = (p < 0) ? 1 : 0;
        if (er == r)
            a0 += *reinterpret_cast<const float*>(Tb + (p & 0x7FFFFFFF));
    }
    float coeff = 1.0f / ((float)ubd[u * 2 + r] + EPSV);
    as[c] = a0 * coeff;
    __syncthreads();
    float acc = 0.f;
    const float* G = g_G[r];
#pragma unroll 4
    for (int k = 0; k < DT; k++) acc += as[k] * G[(long)k * DT + c];
    g_z[r][(long)b * DT + c] = acc;
}

// warp per (b,k); restores g_cnt==0 invariant
__global__ void k_score(const int* __restrict__ users, const int* __restrict__ items,
                        const float* __restrict__ ue, const float* __restrict__ ie,
                        float* out, int lossIdx) {
    __shared__ float l2blk;
    int tg = blockIdx.x * blockDim.x + threadIdx.x;
    if (tg < NTOT) g_cnt[tg] = 0;
    if (threadIdx.x == 0) l2blk = 0.f;
    __syncthreads();
    int w = tg >> 5;
    int lane = threadIdx.x & 31;
    if (w < BB * KK) {
        int b = w / KK;
        int kk = w - b * KK;
        int u = users[b];
        int it = items[w];
        float s1 = 0.f, s2a = 0.f, s2b = 0.f, l2i = 0.f, l2u = 0.f;
        const float* z0 = g_z[0] + (long)b * DT;
        const float* z1 = g_z[1] + (long)b * DT;
#pragma unroll
        for (int s = 0; s < 2; s++) {
            int c = lane + 32 * s;
            {
                float bu = ue[(long)u * DD + c];
                float bi = ie[(long)it * DD + c];
                s1 += bu * bi; l2i += bi * bi;
                if (kk == 0) l2u += bu * bu;
                s2a += z0[c] * bi;
                s2b += z1[c] * bi;
            }
            {
                float bu = g_U1[(long)u * DD + c];
                float bi = g_I1[(long)it * DD + c];
                s1 += bu * bi; l2i += bi * bi;
                if (kk == 0) l2u += bu * bu;
                s2a += z0[64 + c] * g_S1[0][(long)it * DD + c];
                s2b += z1[64 + c] * g_S1[1][(long)it * DD + c];
            }
            {
                float bu = g_U2[(long)u * DD + c];
                float bi = g_I2[(long)it * DD + c];
                s1 += bu * bi; l2i += bi * bi;
                if (kk == 0) l2u += bu * bu;
                s2a += z0[128 + c] * g_S2[0][(long)it * DD + c];
                s2b += z1[128 + c] * g_S2[1][(long)it * DD + c];
            }
        }
#pragma unroll
        for (int off = 16; off; off >>= 1) {
            s1  += __shfl_down_sync(0xffffffffu, s1, off);
            s2a += __shfl_down_sync(0xffffffffu, s2a, off);
            s2b += __shfl_down_sync(0xffffffffu, s2b, off);
            l2i += __shfl_down_sync(0xffffffffu, l2i, off);
            if (kk == 0) l2u += __shfl_down_sync(0xffffffffu, l2u, off);
        }
        if (lane == 0) {
            out[w] = 0.5f * s1 + 0.25f * (s2a + s2b);
            atomicAdd(&l2blk, l2i + (kk == 0 ? (float)KK * l2u : 0.f));
        }
    }
    __syncthreads();
    if (threadIdx.x == 0) atomicAdd(out + lossIdx, 1e-4f * l2blk);
}

// ---------------- launch ----------------
extern "C" void kernel_launch(void* const* d_in, const int* in_sizes, int n_in,
                              void* d_out, int out_size) {
    const float* ue    = (const float*)d_in[0];
    const float* ie    = (const float*)d_in[1];
    const float* W_ui  = (const float*)d_in[2];
    const float* W_ii  = (const float*)d_in[3];
    const float* bW    = (const float*)d_in[4];
    const float* mgnn  = (const float*)d_in[5];
    const int* rel_r   = (const int*)d_in[6];
    const int* rel_c   = (const int*)d_in[7];
    const int* tr_r    = (const int*)d_in[8];
    const int* tr_c    = (const int*)d_in[9];
    const int* ig_r    = (const int*)d_in[10];
    const int* ig_c    = (const int*)d_in[11];
    const int* ubd     = (const int*)d_in[12];
    const int* igd     = (const int*)d_in[13];
    const int* users   = (const int*)d_in[14];
    const int* items   = (const int*)d_in[15];
    float* out = (float*)d_out;
    int lossIdx = out_size - 1;

    const int T = 256;
    auto g = [](long n, int t) { return (int)((n + t - 1) / t); };

    float *U1, *U2, *I1, *I2, *S10, *S11, *S20, *S21;
    cudaGetSymbolAddress((void**)&U1,  g_U1);
    cudaGetSymbolAddress((void**)&U2,  g_U2);
    cudaGetSymbolAddress((void**)&I1,  g_I1);
    cudaGetSymbolAddress((void**)&I2,  g_I2);
    cudaGetSymbolAddress((void**)&S10, g_S1);
    cudaGetSymbolAddress((void**)&S20, g_S2);
    S11 = S10 + I_NN * DD;
    S21 = S20 + I_NN * DD;

    // 1-3: init + CSR build
    k_init_hist<<<g(ETOT, T), T>>>(ubd, igd, mgnn, rel_r, tr_c, ig_r);
    k_scan<<<4, 1024>>>();
    k_place_all<<<g(ETOT, T), T>>>(rel_r, rel_c, tr_r, tr_c, ig_r, ig_c);

    // 4-7: two propagation layers (layer-0 tables ARE the inputs)
    {
        dim3 gg(g(U_NN, 64), 4);
        k_gather_all<<<g((long)(U_NN + 3 * I_NN) * 16, T), T>>>(ue, ie);
        k_gemm_all<<<gg, 256>>>(W_ui, W_ii, W_ii + (long)LL * DD * DD,
                                U1, I1, S10, S11);
        k_gather_all<<<g((long)(U_NN + 3 * I_NN) * 16, T), T>>>(U1, I1);
        k_gemm_all<<<gg, 256>>>(W_ui + (long)DD * DD,
                                W_ii + (long)DD * DD,
                                W_ii + (long)(LL + 1) * DD * DD,
                                U2, I2, S20, S21);
    }

    // 8-10: scoring
    {
        dim3 ggG(6, 6, 2);
        k_G<<<ggG, 256>>>(bW, out, lossIdx);
    }
    {
        dim3 gz(BB, RR);
        k_aggsel_z<<<gz, DT>>>(users, ubd, ie);
    }
    k_score<<<g((long)BB * KK * 32, T), T>>>(users, items, ue, ie, out, lossIdx);
}